// round 4
// baseline (speedup 1.0000x reference)
// R3: resubmission of R2 kernel (R2 bench was an infra failure: container died
// twice; no kernel-attributable evidence). Dtype-probe routing fix from R1 intact.
#include <cuda_runtime.h>

// Problem constants
#define B_TOK 8192
#define H_DIM 1024
#define O_DIM 256
#define E_NUM 16
#define CMAP  1000

// Tiling
#define M_TILE 64   // tokens per block
#define KC 32       // k-chunk (floats)
#define KP 16       // float2 pairs per chunk

// Routing scratch (no allocation allowed -> device globals)
__device__ int d_count[E_NUM];
__device__ int d_list[E_NUM * B_TOK];
__device__ int d_odd_nonzero;   // probe: any nonzero odd int32 slot in num?

__global__ void zero_counts_kernel() {
    if (threadIdx.x < E_NUM) d_count[threadIdx.x] = 0;
    if (threadIdx.x == 0) d_odd_nonzero = 0;
}

// Dtype probe: view num as int32. int64 values <1000 -> all odd slots zero.
// Reads only 8192 int32 = 32KB, safe for both int32 and int64 layouts.
__global__ void probe_kernel(const int* __restrict__ num32) {
    int i = blockIdx.x * blockDim.x + threadIdx.x;  // 0..4095
    if (i < B_TOK / 2) {
        if (num32[2 * i + 1] != 0) atomicOr(&d_odd_nonzero, 1);
    }
}

__global__ void route_kernel(const void* __restrict__ num_v,
                             const void* __restrict__ c_v) {
    int i = blockIdx.x * blockDim.x + threadIdx.x;
    if (i >= B_TOK) return;
    const bool is64 = (d_odd_nonzero == 0);
    long long v;
    if (is64) v = ((const long long*)num_v)[i];
    else      v = (long long)((const int*)num_v)[i];
    v = min(max(v, 0LL), (long long)(CMAP - 1));
    int e;
    if (is64) e = (int)((const long long*)c_v)[v];
    else      e = ((const int*)c_v)[v];
    e = min(max(e, 0), E_NUM - 1);
    int pos = atomicAdd(&d_count[e], 1);
    d_list[e * B_TOK + pos] = i;
}

// Packed dual-FMA (sm_100+): 2 fp32 MACs per instruction.
__device__ __forceinline__ void fma2(unsigned long long& d,
                                     unsigned long long a,
                                     unsigned long long b) {
    asm("fma.rn.f32x2 %0, %1, %2, %0;" : "+l"(d) : "l"(a), "l"(b));
}

__global__ void __launch_bounds__(256, 1)
moe_gemm_kernel(const float* __restrict__ x, const float* __restrict__ W,
                const float* __restrict__ bias, float* __restrict__ out) {
    // Shared staging. Row stride = KP+1 = 17 float2 (odd 8B stride -> conflict-free
    // 64-bit LDS across half-warps).
    __shared__ float2 x_s[M_TILE][KP + 1];
    __shared__ float2 w_s[O_DIM][KP + 1];
    __shared__ int s_tok[M_TILE];

    const int e = blockIdx.y;
    const int cnt = d_count[e];
    const int t0 = blockIdx.x * M_TILE;
    if (t0 >= cnt) return;

    const int tid = threadIdx.x;

    // Load this tile's token indices (clamp duplicates for partial tiles;
    // duplicate compute is harmless, stores are guarded).
    if (tid < M_TILE) {
        int idx = t0 + tid;
        s_tok[tid] = d_list[e * B_TOK + min(idx, cnt - 1)];
    }
    __syncthreads();

    const int tok_grp = tid >> 5;   // 0..7  (all lanes of a warp share -> x broadcast)
    const int o_grp   = tid & 31;   // 0..31 (lane id -> coalesced stores)

    unsigned long long acc[8][8];
#pragma unroll
    for (int i = 0; i < 8; i++)
#pragma unroll
        for (int j = 0; j < 8; j++) acc[i][j] = 0ull;

    const float* Wp = W + (size_t)e * O_DIM * H_DIM;

    for (int k0 = 0; k0 < H_DIM; k0 += KC) {
        // Stage x chunk: 64 rows x 8 float4 (512 float4, 2 per thread)
#pragma unroll
        for (int j = 0; j < 2; j++) {
            int idx = tid + 256 * j;
            int r = idx >> 3;
            int q = idx & 7;
            float4 v = *(const float4*)(x + (size_t)s_tok[r] * H_DIM + k0 + q * 4);
            x_s[r][q * 2]     = make_float2(v.x, v.y);
            x_s[r][q * 2 + 1] = make_float2(v.z, v.w);
        }
        // Stage W chunk: 256 rows x 8 float4 (2048 float4, 8 per thread)
#pragma unroll
        for (int j = 0; j < 8; j++) {
            int idx = tid + 256 * j;
            int r = idx >> 3;
            int q = idx & 7;
            float4 v = *(const float4*)(Wp + (size_t)r * H_DIM + k0 + q * 4);
            w_s[r][q * 2]     = make_float2(v.x, v.y);
            w_s[r][q * 2 + 1] = make_float2(v.z, v.w);
        }
        __syncthreads();

#pragma unroll 4
        for (int p = 0; p < KP; p++) {
            unsigned long long xv[8], wv[8];
#pragma unroll
            for (int i = 0; i < 8; i++)
                xv[i] = *(const unsigned long long*)&x_s[tok_grp * 8 + i][p];
#pragma unroll
            for (int j = 0; j < 8; j++)
                wv[j] = *(const unsigned long long*)&w_s[o_grp + 32 * j][p];
#pragma unroll
            for (int i = 0; i < 8; i++)
#pragma unroll
                for (int j = 0; j < 8; j++)
                    fma2(acc[i][j], xv[i], wv[j]);
        }
        __syncthreads();
    }

    // Epilogue: horizontal add, bias, sigmoid, guarded coalesced store.
#pragma unroll
    for (int i = 0; i < 8; i++) {
        int slot = tok_grp * 8 + i;
        if (t0 + slot >= cnt) continue;
        int tok = s_tok[slot];
#pragma unroll
        for (int j = 0; j < 8; j++) {
            int o = o_grp + 32 * j;
            float2 v = *(float2*)&acc[i][j];
            float z = v.x + v.y + bias[e * O_DIM + o];
            out[(size_t)tok * O_DIM + o] = 1.0f / (1.0f + __expf(-z));
        }
    }
}

extern "C" void kernel_launch(void* const* d_in, const int* in_sizes, int n_in,
                              void* d_out, int out_size) {
    const float* x   = (const float*)d_in[0];   // [B, H] f32
    const float* W   = (const float*)d_in[1];   // [E, O, H] f32
    const float* b   = (const float*)d_in[2];   // [E, O] f32
    const void*  num = d_in[3];                 // [B] int32 or int64
    const void*  c   = d_in[4];                 // [CMAP] int32 or int64
    float* out = (float*)d_out;                 // [B, O] f32

    zero_counts_kernel<<<1, 32>>>();
    probe_kernel<<<(B_TOK / 2 + 255) / 256, 256>>>((const int*)num);
    route_kernel<<<B_TOK / 256, 256>>>(num, c);
    dim3 grid(B_TOK / M_TILE, E_NUM);
    moe_gemm_kernel<<<grid, 256>>>(x, W, b, out);
}

// round 8
// speedup vs baseline: 1.5299x; 1.5299x over previous
// R8: R6 with cp.async alignment fix: XS_STRIDE 34 -> 36 floats (row stride
// must be a 16B multiple for cp.async.cg 16B). Everything else unchanged.
#include <cuda_runtime.h>
#include <cuda_bf16.h>
#include <cstdint>

#define B_TOK 8192
#define H_DIM 1024
#define O_DIM 256
#define E_NUM 16
#define CMAP  1000

#define M_TILE 64
#define KC 32
#define NCHUNK (H_DIM / KC)         // 32
#define MAX_TILES 144               // sum ceil(cnt_e/64) <= 128 + 16
#define XS_STRIDE 36                // f32 row stride; 36*4=144B = 16B multiple
#define XS_ELEMS (M_TILE * XS_STRIDE)   // 2304 floats
#define WS_ELEMS (O_DIM * XS_STRIDE)    // 9216 floats
#define STAGE_F (XS_ELEMS + WS_ELEMS)   // 11520 floats
#define DYN_SMEM (2 * STAGE_F * 4)      // 92160 bytes

// ---------------- routing scratch ----------------
__device__ int d_count[E_NUM];
__device__ int d_list[E_NUM * B_TOK];
__device__ int d_odd_nonzero;
__device__ int d_tile_e[MAX_TILES];
__device__ int d_tile_l[MAX_TILES];
__device__ int d_tile_n;

__global__ void zero_counts_kernel() {
    if (threadIdx.x < E_NUM) d_count[threadIdx.x] = 0;
    if (threadIdx.x == 0) d_odd_nonzero = 0;
}

// Dtype probe: view num as int32; true-int64 values <1000 -> all odd slots zero.
__global__ void probe_kernel(const int* __restrict__ num32) {
    int i = blockIdx.x * blockDim.x + threadIdx.x;
    if (i < B_TOK / 2) {
        if (num32[2 * i + 1] != 0) atomicOr(&d_odd_nonzero, 1);
    }
}

__global__ void route_kernel(const void* __restrict__ num_v,
                             const void* __restrict__ c_v) {
    int i = blockIdx.x * blockDim.x + threadIdx.x;
    if (i >= B_TOK) return;
    const bool is64 = (d_odd_nonzero == 0);
    long long v;
    if (is64) v = ((const long long*)num_v)[i];
    else      v = (long long)((const int*)num_v)[i];
    v = min(max(v, 0LL), (long long)(CMAP - 1));
    int e;
    if (is64) e = (int)((const long long*)c_v)[v];
    else      e = ((const int*)c_v)[v];
    e = min(max(e, 0), E_NUM - 1);
    int pos = atomicAdd(&d_count[e], 1);
    d_list[e * B_TOK + pos] = i;
}

__global__ void tilemap_kernel() {
    if (threadIdx.x == 0) {
        int t = 0;
        for (int e = 0; e < E_NUM; e++) {
            int nt = (d_count[e] + M_TILE - 1) / M_TILE;
            for (int i = 0; i < nt; i++) { d_tile_e[t] = e; d_tile_l[t] = i; t++; }
        }
        d_tile_n = t;
    }
}

// ---------------- helpers ----------------
__device__ __forceinline__ uint32_t smem_u32(const void* p) {
    uint32_t a;
    asm("{ .reg .u64 t; cvta.to.shared.u64 t, %1; cvt.u32.u64 %0, t; }"
        : "=r"(a) : "l"(p));
    return a;
}

__device__ __forceinline__ void cp16(uint32_t dst, const void* src) {
    asm volatile("cp.async.cg.shared.global [%0], [%1], 16;"
                 :: "r"(dst), "l"(src));
}
#define CP_COMMIT() asm volatile("cp.async.commit_group;" ::: "memory")
#define CP_WAIT(n)  asm volatile("cp.async.wait_group %0;" :: "n"(n) : "memory")

// f32 pair -> bf16x2 hi + bf16x2 lo (residual). Exact hi reconstruct via bit ops.
__device__ __forceinline__ void cvt2(float2 v, uint32_t& hi, uint32_t& lo) {
    uint32_t h;
    asm("cvt.rn.bf16x2.f32 %0, %1, %2;" : "=r"(h) : "f"(v.y), "f"(v.x));
    float h0 = __uint_as_float(h << 16);
    float h1 = __uint_as_float(h & 0xFFFF0000u);
    float r0 = v.x - h0, r1 = v.y - h1;
    uint32_t l;
    asm("cvt.rn.bf16x2.f32 %0, %1, %2;" : "=r"(l) : "f"(r1), "f"(r0));
    hi = h; lo = l;
}

__device__ __forceinline__ void mma_bf16(float* d, const uint32_t* a,
                                         const uint32_t* b) {
    asm volatile(
        "mma.sync.aligned.m16n8k16.row.col.f32.bf16.bf16.f32 "
        "{%0,%1,%2,%3}, {%4,%5,%6,%7}, {%8,%9}, {%0,%1,%2,%3};"
        : "+f"(d[0]), "+f"(d[1]), "+f"(d[2]), "+f"(d[3])
        : "r"(a[0]), "r"(a[1]), "r"(a[2]), "r"(a[3]), "r"(b[0]), "r"(b[1]));
}

// ---------------- grouped GEMM: 64x256x1024 per CTA ----------------
__global__ void __launch_bounds__(256, 1)
moe_mma_gemm(const float* __restrict__ x, const float* __restrict__ W,
             const float* __restrict__ bias, float* __restrict__ out) {
    extern __shared__ float sm[];
    __shared__ int s_tok[M_TILE];

    const int t = blockIdx.x;
    if (t >= d_tile_n) return;
    const int e = d_tile_e[t];
    const int lt = d_tile_l[t];
    const int cnt = d_count[e];
    const int tid = threadIdx.x, lane = tid & 31, wid = tid >> 5;
    const int mw = wid & 1;     // 0..1 : M groups of 32
    const int nw = wid >> 1;    // 0..3 : N groups of 64

    if (tid < M_TILE) {
        int slot = lt * M_TILE + tid;
        s_tok[tid] = d_list[e * B_TOK + min(slot, cnt - 1)];
    }
    __syncthreads();

    const float* Wp = W + (size_t)e * O_DIM * H_DIM;
    float* const xs[2] = {sm, sm + STAGE_F};
    float* const ws[2] = {sm + XS_ELEMS, sm + STAGE_F + XS_ELEMS};

    float acc[2][8][4];
#pragma unroll
    for (int i = 0; i < 2; i++)
#pragma unroll
        for (int j = 0; j < 8; j++)
#pragma unroll
            for (int k = 0; k < 4; k++) acc[i][j][k] = 0.0f;

#define ISSUE_CHUNK(chunk) do {                                               \
        int _b = (chunk) & 1;                                                 \
        uint32_t _xd = smem_u32(xs[_b]), _wd = smem_u32(ws[_b]);              \
        _Pragma("unroll")                                                     \
        for (int _i = 0; _i < 2; _i++) {                                      \
            int _idx = tid + 256 * _i, _r = _idx >> 3, _q = _idx & 7;         \
            cp16(_xd + (_r * XS_STRIDE + _q * 4) * 4,                         \
                 x + (size_t)s_tok[_r] * H_DIM + (chunk) * KC + _q * 4);      \
        }                                                                     \
        _Pragma("unroll")                                                     \
        for (int _i = 0; _i < 8; _i++) {                                      \
            int _idx = tid + 256 * _i, _r = _idx >> 3, _q = _idx & 7;         \
            cp16(_wd + (_r * XS_STRIDE + _q * 4) * 4,                         \
                 Wp + (size_t)_r * H_DIM + (chunk) * KC + _q * 4);            \
        }                                                                     \
        CP_COMMIT();                                                          \
    } while (0)

    ISSUE_CHUNK(0);
    const int g = lane >> 2, q4 = lane & 3;

    for (int c = 0; c < NCHUNK; c++) {
        if (c + 1 < NCHUNK) { ISSUE_CHUNK(c + 1); CP_WAIT(1); }
        else                { CP_WAIT(0); }
        __syncthreads();
        const float* xb = xs[c & 1];
        const float* wb = ws[c & 1];

#pragma unroll
        for (int kk = 0; kk < 2; kk++) {     // two k16 steps per 32-chunk
            const int k0 = kk * 16;
            uint32_t ah[2][4], al[2][4];
#pragma unroll
            for (int mt = 0; mt < 2; mt++)
#pragma unroll
                for (int cc = 0; cc < 2; cc++)
#pragma unroll
                    for (int rr = 0; rr < 2; rr++) {
                        int row = mw * 32 + mt * 16 + g + rr * 8;
                        int col = k0 + q4 * 2 + cc * 8;
                        float2 v = *(const float2*)&xb[row * XS_STRIDE + col];
                        cvt2(v, ah[mt][rr + cc * 2], al[mt][rr + cc * 2]);
                    }
#pragma unroll
            for (int nt = 0; nt < 8; nt++) {
                int n = nw * 64 + nt * 8 + g;
                uint32_t bh[2], bl[2];
#pragma unroll
                for (int rr = 0; rr < 2; rr++) {
                    int k = k0 + q4 * 2 + rr * 8;
                    float2 v = *(const float2*)&wb[n * XS_STRIDE + k];
                    cvt2(v, bh[rr], bl[rr]);
                }
#pragma unroll
                for (int mt = 0; mt < 2; mt++) {
                    mma_bf16(acc[mt][nt], ah[mt], bh);
                    mma_bf16(acc[mt][nt], ah[mt], bl);
                    mma_bf16(acc[mt][nt], al[mt], bh);
                }
            }
        }
        __syncthreads();
    }
#undef ISSUE_CHUNK

    // Epilogue: bias + sigmoid, guarded float2 stores.
#pragma unroll
    for (int mt = 0; mt < 2; mt++)
#pragma unroll
        for (int rr = 0; rr < 2; rr++) {
            int rowslot = mw * 32 + mt * 16 + g + rr * 8;
            if (lt * M_TILE + rowslot >= cnt) continue;
            int tok = s_tok[rowslot];
#pragma unroll
            for (int nt = 0; nt < 8; nt++) {
                int col = nw * 64 + nt * 8 + q4 * 2;
                float2 bb = *(const float2*)&bias[e * O_DIM + col];
                float z0 = acc[mt][nt][rr * 2 + 0] + bb.x;
                float z1 = acc[mt][nt][rr * 2 + 1] + bb.y;
                float2 o;
                o.x = 1.0f / (1.0f + __expf(-z0));
                o.y = 1.0f / (1.0f + __expf(-z1));
                *(float2*)&out[(size_t)tok * O_DIM + col] = o;
            }
        }
}

// ---------------- launch ----------------
extern "C" void kernel_launch(void* const* d_in, const int* in_sizes, int n_in,
                              void* d_out, int out_size) {
    const float* x   = (const float*)d_in[0];   // [B, H] f32
    const float* W   = (const float*)d_in[1];   // [E, O, H] f32
    const float* b   = (const float*)d_in[2];   // [E, O] f32
    const void*  num = d_in[3];                 // [B] int32 or int64
    const void*  c   = d_in[4];                 // [CMAP] int32 or int64
    float* out = (float*)d_out;                 // [B, O] f32

    cudaFuncSetAttribute(moe_mma_gemm,
                         cudaFuncAttributeMaxDynamicSharedMemorySize, DYN_SMEM);

    zero_counts_kernel<<<1, 32>>>();
    probe_kernel<<<(B_TOK / 2 + 255) / 256, 256>>>((const int*)num);
    route_kernel<<<B_TOK / 256, 256>>>(num, c);
    tilemap_kernel<<<1, 32>>>();
    moe_mma_gemm<<<MAX_TILES, 256, DYN_SMEM>>>(x, W, b, out);
}

// round 9
// speedup vs baseline: 1.6538x; 1.0810x over previous
// R9: 512-thread CTA (4 warps/SMSP for latency hiding), warp grid 2Mx8N;
// tilemap kernel folded into GEMM block prologue. Core 3-term bf16 mma.sync
// mainloop and routing unchanged from passing R8.
#include <cuda_runtime.h>
#include <cuda_bf16.h>
#include <cstdint>

#define B_TOK 8192
#define H_DIM 1024
#define O_DIM 256
#define E_NUM 16
#define CMAP  1000

#define M_TILE 64
#define KC 32
#define NCHUNK (H_DIM / KC)         // 32
#define MAX_TILES 144               // sum ceil(cnt_e/64) <= 128 + 16
#define XS_STRIDE 36                // f32 row stride; 144B = 16B multiple
#define XS_ELEMS (M_TILE * XS_STRIDE)
#define WS_ELEMS (O_DIM * XS_STRIDE)
#define STAGE_F (XS_ELEMS + WS_ELEMS)
#define DYN_SMEM (2 * STAGE_F * 4)  // 92160 bytes

// ---------------- routing scratch ----------------
__device__ int d_count[E_NUM];
__device__ int d_list[E_NUM * B_TOK];
__device__ int d_odd_nonzero;

__global__ void zero_counts_kernel() {
    if (threadIdx.x < E_NUM) d_count[threadIdx.x] = 0;
    if (threadIdx.x == 0) d_odd_nonzero = 0;
}

// Dtype probe: view num as int32; true-int64 values <1000 -> all odd slots zero.
__global__ void probe_kernel(const int* __restrict__ num32) {
    int i = blockIdx.x * blockDim.x + threadIdx.x;
    if (i < B_TOK / 2) {
        if (num32[2 * i + 1] != 0) atomicOr(&d_odd_nonzero, 1);
    }
}

__global__ void route_kernel(const void* __restrict__ num_v,
                             const void* __restrict__ c_v) {
    int i = blockIdx.x * blockDim.x + threadIdx.x;
    if (i >= B_TOK) return;
    const bool is64 = (d_odd_nonzero == 0);
    long long v;
    if (is64) v = ((const long long*)num_v)[i];
    else      v = (long long)((const int*)num_v)[i];
    v = min(max(v, 0LL), (long long)(CMAP - 1));
    int e;
    if (is64) e = (int)((const long long*)c_v)[v];
    else      e = ((const int*)c_v)[v];
    e = min(max(e, 0), E_NUM - 1);
    int pos = atomicAdd(&d_count[e], 1);
    d_list[e * B_TOK + pos] = i;
}

// ---------------- helpers ----------------
__device__ __forceinline__ uint32_t smem_u32(const void* p) {
    uint32_t a;
    asm("{ .reg .u64 t; cvta.to.shared.u64 t, %1; cvt.u32.u64 %0, t; }"
        : "=r"(a) : "l"(p));
    return a;
}

__device__ __forceinline__ void cp16(uint32_t dst, const void* src) {
    asm volatile("cp.async.cg.shared.global [%0], [%1], 16;"
                 :: "r"(dst), "l"(src));
}
#define CP_COMMIT() asm volatile("cp.async.commit_group;" ::: "memory")
#define CP_WAIT(n)  asm volatile("cp.async.wait_group %0;" :: "n"(n) : "memory")

// f32 pair -> bf16x2 hi + bf16x2 lo (residual). Exact hi reconstruct via bit ops.
__device__ __forceinline__ void cvt2(float2 v, uint32_t& hi, uint32_t& lo) {
    uint32_t h;
    asm("cvt.rn.bf16x2.f32 %0, %1, %2;" : "=r"(h) : "f"(v.y), "f"(v.x));
    float h0 = __uint_as_float(h << 16);
    float h1 = __uint_as_float(h & 0xFFFF0000u);
    float r0 = v.x - h0, r1 = v.y - h1;
    uint32_t l;
    asm("cvt.rn.bf16x2.f32 %0, %1, %2;" : "=r"(l) : "f"(r1), "f"(r0));
    hi = h; lo = l;
}

__device__ __forceinline__ void mma_bf16(float* d, const uint32_t* a,
                                         const uint32_t* b) {
    asm volatile(
        "mma.sync.aligned.m16n8k16.row.col.f32.bf16.bf16.f32 "
        "{%0,%1,%2,%3}, {%4,%5,%6,%7}, {%8,%9}, {%0,%1,%2,%3};"
        : "+f"(d[0]), "+f"(d[1]), "+f"(d[2]), "+f"(d[3])
        : "r"(a[0]), "r"(a[1]), "r"(a[2]), "r"(a[3]), "r"(b[0]), "r"(b[1]));
}

// ---------------- grouped GEMM: 64x256x1024 per CTA, 512 threads ----------------
__global__ void __launch_bounds__(512, 1)
moe_mma_gemm(const float* __restrict__ x, const float* __restrict__ W,
             const float* __restrict__ bias, float* __restrict__ out) {
    extern __shared__ float sm[];
    __shared__ int s_tok[M_TILE];

    // Derive (expert, local tile) from blockIdx via scan of d_count (L1-cached).
    const int t = blockIdx.x;
    int e = 0, base = 0;
#pragma unroll
    for (int i = 0; i < E_NUM; i++) {
        int nt = (d_count[i] + M_TILE - 1) / M_TILE;
        if (t >= base && t < base + nt) { e = i + 1; }
        base += nt;
    }
    if (e == 0) { if (t >= base) return; }   // t beyond total tiles
    // recompute lt for the found expert
    e -= 1;
    if (e < 0) return;
    base = 0;
    for (int i = 0; i < e; i++) base += (d_count[i] + M_TILE - 1) / M_TILE;
    const int lt = t - base;
    const int cnt = d_count[e];

    const int tid = threadIdx.x, lane = tid & 31, wid = tid >> 5;
    const int mw = wid & 1;     // 0..1 : M groups of 32
    const int nw = wid >> 1;    // 0..7 : N groups of 32

    if (tid < M_TILE) {
        int slot = lt * M_TILE + tid;
        s_tok[tid] = d_list[e * B_TOK + min(slot, cnt - 1)];
    }
    __syncthreads();

    const float* Wp = W + (size_t)e * O_DIM * H_DIM;
    float* const xs[2] = {sm, sm + STAGE_F};
    float* const ws[2] = {sm + XS_ELEMS, sm + STAGE_F + XS_ELEMS};

    float acc[2][4][4];
#pragma unroll
    for (int i = 0; i < 2; i++)
#pragma unroll
        for (int j = 0; j < 4; j++)
#pragma unroll
            for (int k = 0; k < 4; k++) acc[i][j][k] = 0.0f;

#define ISSUE_CHUNK(chunk) do {                                               \
        int _b = (chunk) & 1;                                                 \
        uint32_t _xd = smem_u32(xs[_b]), _wd = smem_u32(ws[_b]);              \
        {   /* x: 512 float4, 1 per thread */                                 \
            int _r = tid >> 3, _q = tid & 7;                                  \
            cp16(_xd + (_r * XS_STRIDE + _q * 4) * 4,                         \
                 x + (size_t)s_tok[_r] * H_DIM + (chunk) * KC + _q * 4);      \
        }                                                                     \
        _Pragma("unroll")                                                     \
        for (int _i = 0; _i < 4; _i++) {  /* W: 2048 float4, 4 per thread */  \
            int _idx = tid + 512 * _i, _r = _idx >> 3, _q = _idx & 7;         \
            cp16(_wd + (_r * XS_STRIDE + _q * 4) * 4,                         \
                 Wp + (size_t)_r * H_DIM + (chunk) * KC + _q * 4);            \
        }                                                                     \
        CP_COMMIT();                                                          \
    } while (0)

    ISSUE_CHUNK(0);
    const int g = lane >> 2, q4 = lane & 3;

    for (int c = 0; c < NCHUNK; c++) {
        if (c + 1 < NCHUNK) { ISSUE_CHUNK(c + 1); CP_WAIT(1); }
        else                { CP_WAIT(0); }
        __syncthreads();
        const float* xb = xs[c & 1];
        const float* wb = ws[c & 1];

#pragma unroll
        for (int kk = 0; kk < 2; kk++) {     // two k16 steps per 32-chunk
            const int k0 = kk * 16;
            uint32_t ah[2][4], al[2][4];
#pragma unroll
            for (int mt = 0; mt < 2; mt++)
#pragma unroll
                for (int cc = 0; cc < 2; cc++)
#pragma unroll
                    for (int rr = 0; rr < 2; rr++) {
                        int row = mw * 32 + mt * 16 + g + rr * 8;
                        int col = k0 + q4 * 2 + cc * 8;
                        float2 v = *(const float2*)&xb[row * XS_STRIDE + col];
                        cvt2(v, ah[mt][rr + cc * 2], al[mt][rr + cc * 2]);
                    }
#pragma unroll
            for (int nt = 0; nt < 4; nt++) {
                int n = nw * 32 + nt * 8 + g;
                uint32_t bh[2], bl[2];
#pragma unroll
                for (int rr = 0; rr < 2; rr++) {
                    int k = k0 + q4 * 2 + rr * 8;
                    float2 v = *(const float2*)&wb[n * XS_STRIDE + k];
                    cvt2(v, bh[rr], bl[rr]);
                }
#pragma unroll
                for (int mt = 0; mt < 2; mt++) {
                    mma_bf16(acc[mt][nt], ah[mt], bh);
                    mma_bf16(acc[mt][nt], ah[mt], bl);
                    mma_bf16(acc[mt][nt], al[mt], bh);
                }
            }
        }
        __syncthreads();
    }
#undef ISSUE_CHUNK

    // Epilogue: bias + sigmoid, guarded float2 stores.
#pragma unroll
    for (int mt = 0; mt < 2; mt++)
#pragma unroll
        for (int rr = 0; rr < 2; rr++) {
            int rowslot = mw * 32 + mt * 16 + g + rr * 8;
            if (lt * M_TILE + rowslot >= cnt) continue;
            int tok = s_tok[rowslot];
#pragma unroll
            for (int nt = 0; nt < 4; nt++) {
                int col = nw * 32 + nt * 8 + q4 * 2;
                float2 bb = *(const float2*)&bias[e * O_DIM + col];
                float z0 = acc[mt][nt][rr * 2 + 0] + bb.x;
                float z1 = acc[mt][nt][rr * 2 + 1] + bb.y;
                float2 o;
                o.x = 1.0f / (1.0f + __expf(-z0));
                o.y = 1.0f / (1.0f + __expf(-z1));
                *(float2*)&out[(size_t)tok * O_DIM + col] = o;
            }
        }
}

// ---------------- launch ----------------
extern "C" void kernel_launch(void* const* d_in, const int* in_sizes, int n_in,
                              void* d_out, int out_size) {
    const float* x   = (const float*)d_in[0];   // [B, H] f32
    const float* W   = (const float*)d_in[1];   // [E, O, H] f32
    const float* b   = (const float*)d_in[2];   // [E, O] f32
    const void*  num = d_in[3];                 // [B] int32 or int64
    const void*  c   = d_in[4];                 // [CMAP] int32 or int64
    float* out = (float*)d_out;                 // [B, O] f32

    cudaFuncSetAttribute(moe_mma_gemm,
                         cudaFuncAttributeMaxDynamicSharedMemorySize, DYN_SMEM);

    zero_counts_kernel<<<1, 32>>>();
    probe_kernel<<<(B_TOK / 2 + 255) / 256, 256>>>((const int*)num);
    route_kernel<<<B_TOK / 256, 256>>>(num, c);
    moe_mma_gemm<<<MAX_TILES, 512, DYN_SMEM>>>(x, W, b, out);
}